// round 1
// baseline (speedup 1.0000x reference)
#include <cuda_runtime.h>
#include <cstdint>

#define NB_IMG   16
#define NA       22743
#define NCH      85
#define NCLS     80
#define PRE      1000
#define PADN     1024
#define SORTN    4096
#define CAP      32768
#define NBINS    8192
#define MAXDET   300
#define CONF_TH  0.2f
#define NMS_TH   0.45f

static __device__ __constant__ unsigned B09 = 0x3F666666u; // bits(0.9f)

__device__ unsigned            g_hist[NB_IMG][NBINS];
__device__ unsigned            g_hist2[NB_IMG][NBINS];
__device__ unsigned            g_cnt02[NB_IMG];
__device__ unsigned            g_candcnt[NB_IMG];
__device__ unsigned long long  g_cand[NB_IMG][CAP];
__device__ unsigned            g_thr[NB_IMG];
__device__ unsigned            g_M[NB_IMG];
__device__ int                 g_flag[NB_IMG];
__device__ float               g_box[NB_IMG][PADN][4];
__device__ float               g_sbox[NB_IMG][PADN][4];
__device__ float               g_sarea[NB_IMG][PADN];
__device__ float               g_score[NB_IMG][PADN];
__device__ int                 g_label[NB_IMG][PADN];
__device__ unsigned            g_mask[NB_IMG][PADN][32];

// ---------------------------------------------------------------- zero
__global__ void k_zero() {
    int i = blockIdx.x * blockDim.x + threadIdx.x;
    if (i < NB_IMG * NBINS) {
        (&g_hist[0][0])[i]  = 0u;
        (&g_hist2[0][0])[i] = 0u;
    }
    if (i < NB_IMG) {
        g_cnt02[i]   = 0u;
        g_candcnt[i] = 0u;
    }
}

// ---------------------------------------------------------------- main scan
// One thread per anchor: compute 80 scores, count >0.2, hist+push >0.9.
__global__ void k_scan(const float* __restrict__ preds) {
    int a   = blockIdx.x * blockDim.x + threadIdx.x;
    int img = blockIdx.y;
    if (a >= NA) return;
    const float* p = preds + ((size_t)(img * NA + a)) * NCH;
    float conf = p[4];
    int c02 = 0;
    unsigned flatbase = (unsigned)a * NCLS;
#pragma unroll 4
    for (int c = 0; c < NCLS; c++) {
        float s = p[5 + c] * conf;        // classprobs * conf (exact f32 mult)
        if (s > CONF_TH) c02++;
        if (s > 0.9f) {
            unsigned bits = __float_as_uint(s);
            unsigned bin  = (bits - (B09 + 1u)) >> 8;
            if (bin > NBINS - 1) bin = NBINS - 1;
            atomicAdd(&g_hist[img][bin], 1u);
            unsigned pos = atomicAdd(&g_candcnt[img], 1u);
            if (pos < CAP)
                g_cand[img][pos] = ((unsigned long long)bits << 32) |
                                   (unsigned long long)(0xFFFFFFFFu - (flatbase + (unsigned)c));
        }
    }
    if (c02) atomicAdd(&g_cnt02[img], (unsigned)c02);
}

// ---------------------------------------------------------------- threshold from fine hist
__global__ void k_thr() {
    __shared__ unsigned sh[NBINS];
    __shared__ unsigned csum[256];
    int img = blockIdx.x, tid = threadIdx.x;
    for (int i = tid; i < NBINS; i += 256) sh[i] = g_hist[img][i];
    __syncthreads();
    unsigned ssum = 0;
    for (int j = 0; j < 32; j++) ssum += sh[tid * 32 + j];
    csum[tid] = ssum;
    __syncthreads();
    if (tid == 0) {
        unsigned total = 0;
        for (int c = 0; c < 256; c++) total += csum[c];
        if (total >= PRE) {
            unsigned acc = 0, M = 0;
            int bstar = 0;
            for (int c = 255; c >= 0; c--) {
                if (acc + csum[c] >= PRE) {
                    for (int b = c * 32 + 31; b >= c * 32; b--) {
                        acc += sh[b];
                        if (acc >= PRE) { bstar = b; M = acc; break; }
                    }
                    break;
                }
                acc += csum[c];
            }
            if (M > SORTN) { M -= sh[bstar]; bstar++; }   // pathological ties
            g_thr[img]  = B09 + 1u + ((unsigned)bstar << 8);
            g_M[img]    = M;
            g_flag[img] = 0;
        } else {
            g_candcnt[img] = 0;
            if (g_cnt02[img] >= PRE) {
                g_flag[img] = 1;                           // need full-range fallback
            } else {
                g_flag[img] = 2;                           // select everything > 0.2
                g_thr[img]  = 0;
                g_M[img]    = g_cnt02[img];
            }
        }
    }
}

// ---------------------------------------------------------------- fallback hist (rare)
__global__ void k_fbhist(const float* __restrict__ preds) {
    int img = blockIdx.y;
    if (g_flag[img] != 1) return;
    int a = blockIdx.x * blockDim.x + threadIdx.x;
    if (a >= NA) return;
    const float* p = preds + ((size_t)(img * NA + a)) * NCH;
    float conf = p[4];
    for (int c = 0; c < NCLS; c++) {
        float s = p[5 + c] * conf;
        if (s > CONF_TH) {
            unsigned bin = __float_as_uint(s) >> 13;
            if (bin > NBINS - 1) bin = NBINS - 1;
            atomicAdd(&g_hist2[img][bin], 1u);
        }
    }
}

__global__ void k_fbthr() {
    int img = blockIdx.x;
    if (g_flag[img] != 1) return;
    __shared__ unsigned sh[NBINS];
    __shared__ unsigned csum[256];
    int tid = threadIdx.x;
    for (int i = tid; i < NBINS; i += 256) sh[i] = g_hist2[img][i];
    __syncthreads();
    unsigned ssum = 0;
    for (int j = 0; j < 32; j++) ssum += sh[tid * 32 + j];
    csum[tid] = ssum;
    __syncthreads();
    if (tid == 0) {
        unsigned acc = 0, M = 0;
        int bstar = 0;
        for (int c = 255; c >= 0; c--) {
            if (acc + csum[c] >= PRE) {
                for (int b = c * 32 + 31; b >= c * 32; b--) {
                    acc += sh[b];
                    if (acc >= PRE) { bstar = b; M = acc; break; }
                }
                break;
            }
            acc += csum[c];
        }
        if (M > SORTN) { M -= sh[bstar]; bstar++; }
        g_thr[img] = (unsigned)bstar << 13;
        g_M[img]   = M;
    }
}

__global__ void k_fbcompact(const float* __restrict__ preds) {
    int img = blockIdx.y;
    if (g_flag[img] == 0) return;
    int a = blockIdx.x * blockDim.x + threadIdx.x;
    if (a >= NA) return;
    unsigned thr = g_thr[img];
    const float* p = preds + ((size_t)(img * NA + a)) * NCH;
    float conf = p[4];
    unsigned flatbase = (unsigned)a * NCLS;
    for (int c = 0; c < NCLS; c++) {
        float s = p[5 + c] * conf;
        if (s > CONF_TH) {
            unsigned bits = __float_as_uint(s);
            if (bits >= thr) {
                unsigned pos = atomicAdd(&g_candcnt[img], 1u);
                if (pos < CAP)
                    g_cand[img][pos] = ((unsigned long long)bits << 32) |
                                       (unsigned long long)(0xFFFFFFFFu - (flatbase + (unsigned)c));
            }
        }
    }
}

// ---------------------------------------------------------------- sort + gather + shift
__global__ void k_prep(const float* __restrict__ preds) {
    __shared__ unsigned long long keys[SORTN];
    __shared__ unsigned scnt;
    __shared__ float wmax[32];
    __shared__ float s_maxv;
    int img = blockIdx.x, tid = threadIdx.x;
    unsigned thr = g_thr[img];
    unsigned n   = g_candcnt[img]; if (n > CAP) n = CAP;
    if (tid == 0) scnt = 0;
    for (int i = tid; i < SORTN; i += 1024) keys[i] = 0ULL;
    __syncthreads();
    for (unsigned i = tid; i < n; i += 1024) {
        unsigned long long k = g_cand[img][i];
        if ((unsigned)(k >> 32) >= thr) {
            unsigned pos = atomicAdd(&scnt, 1u);
            if (pos < SORTN) keys[pos] = k;
        }
    }
    __syncthreads();
    // bitonic sort, descending
    for (int k2 = 2; k2 <= SORTN; k2 <<= 1)
        for (int j = k2 >> 1; j > 0; j >>= 1) {
            for (int idx = tid; idx < SORTN; idx += 1024) {
                int ixj = idx ^ j;
                if (ixj > idx) {
                    unsigned long long x = keys[idx], y = keys[ixj];
                    bool asc  = (idx & k2) != 0;
                    bool swap = asc ? (x > y) : (x < y);
                    if (swap) { keys[idx] = y; keys[ixj] = x; }
                }
            }
            __syncthreads();
        }
    // decode row tid
    float bx0 = 0.f, bx1 = 0.f, bx2 = 0.f, bx3 = 0.f, s = 0.f;
    int lab = 0;
    float localmax = 0.0f;                 // coords >= 0, so 0 is neutral
    if (tid < PRE) {
        unsigned long long k = keys[tid];
        if (k != 0ULL) {
            unsigned bits = (unsigned)(k >> 32);
            s = __uint_as_float(bits);
            unsigned flat = 0xFFFFFFFFu - (unsigned)(k & 0xFFFFFFFFull);
            int anc = (int)(flat / NCLS);
            lab     = (int)(flat % NCLS);
            const float* bp = preds + ((size_t)(img * NA + anc)) * NCH;
            bx0 = bp[0]; bx1 = bp[1]; bx2 = bp[2]; bx3 = bp[3];
        }
        localmax = fmaxf(fmaxf(bx0, bx1), fmaxf(bx2, bx3));
        g_score[img][tid]  = s;
        g_label[img][tid]  = lab;
        g_box[img][tid][0] = bx0; g_box[img][tid][1] = bx1;
        g_box[img][tid][2] = bx2; g_box[img][tid][3] = bx3;
    }
    // block max reduce
    for (int o = 16; o; o >>= 1) localmax = fmaxf(localmax, __shfl_xor_sync(0xFFFFFFFFu, localmax, o));
    if ((tid & 31) == 0) wmax[tid >> 5] = localmax;
    __syncthreads();
    if (tid < 32) {
        float v = wmax[tid];
        for (int o = 16; o; o >>= 1) v = fmaxf(v, __shfl_xor_sync(0xFFFFFFFFu, v, o));
        if (tid == 0) s_maxv = v;
    }
    __syncthreads();
    float maxv = s_maxv;
    if (tid < PRE) {
        float shift = (float)lab * (maxv + 1.0f);
        float x1 = bx0 + shift, y1 = bx1 + shift, x2 = bx2 + shift, y2 = bx3 + shift;
        g_sbox[img][tid][0] = x1; g_sbox[img][tid][1] = y1;
        g_sbox[img][tid][2] = x2; g_sbox[img][tid][3] = y2;
        g_sarea[img][tid] = fmaxf(x2 - x1, 0.0f) * fmaxf(y2 - y1, 0.0f);
    }
}

// ---------------------------------------------------------------- suppression mask
// blockDim 256 = 8 rows x 32 words; grid (128, 16)
__global__ void k_mask() {
    int img = blockIdx.y;
    int tid = threadIdx.x;
    int i   = blockIdx.x * 8 + (tid >> 5);
    int w   = tid & 31;
    unsigned bitsOut = 0u;
    if (i < PRE) {
        float x1 = g_sbox[img][i][0], y1 = g_sbox[img][i][1];
        float x2 = g_sbox[img][i][2], y2 = g_sbox[img][i][3];
        float ai = g_sarea[img][i];
        int j0 = w * 32;
        for (int jj = 0; jj < 32; jj++) {
            int j = j0 + jj;
            if (j < PRE && j > i) {
                float xj1 = g_sbox[img][j][0], yj1 = g_sbox[img][j][1];
                float xj2 = g_sbox[img][j][2], yj2 = g_sbox[img][j][3];
                float ix1 = fmaxf(x1, xj1), iy1 = fmaxf(y1, yj1);
                float ix2 = fminf(x2, xj2), iy2 = fminf(y2, yj2);
                float inter = fmaxf(ix2 - ix1, 0.0f) * fmaxf(iy2 - iy1, 0.0f);
                float den = ai + g_sarea[img][j];
                den = den - inter;
                den = den + 1e-7f;
                float iou = __fdiv_rn(inter, den);
                if (iou > NMS_TH) bitsOut |= (1u << jj);
            }
        }
    }
    g_mask[img][i][w] = bitsOut;
}

// ---------------------------------------------------------------- serial NMS reduce + output
__global__ void k_final(float* __restrict__ dout) {
    extern __shared__ unsigned smask[];   // PRE*32 words = 128000 B
    int img = blockIdx.x, tid = threadIdx.x;
    const unsigned* gm = &g_mask[img][0][0];
    for (int i = tid; i < PRE * 32; i += 1024) smask[i] = gm[i];
    __syncthreads();
    if (tid < 32) {
        int w = tid;
        unsigned valid = 0u;
        for (int b = 0; b < 32; b++) {
            int i = w * 32 + b;
            if (i < PRE && g_score[img][i] > CONF_TH) valid |= (1u << b);
        }
        unsigned removed = 0u, mykeep = 0u;
        for (int W = 0; W < 32; W++) {
            unsigned kw = 0u;
            if (w == W) {
                unsigned rW = removed;
                for (int b = 0; b < 32; b++) {
                    int i = W * 32 + b;
                    if (i >= PRE) break;
                    if (((valid >> b) & 1u) && !((rW >> b) & 1u)) {
                        kw |= (1u << b);
                        rW |= smask[i * 32 + W];
                    }
                }
                removed = rW;
            }
            kw = __shfl_sync(0xFFFFFFFFu, kw, W);
            unsigned m = kw;
            while (m) {
                int b = __ffs(m) - 1; m &= m - 1;
                removed |= smask[(W * 32 + b) * 32 + w];
            }
            if (w == W) mykeep = kw;
            __syncwarp();
        }
        // output: kept entries in order (already score-descending), cap 300, pad rest
        int cnt = __popc(mykeep);
        int pre = cnt;
        for (int o = 1; o < 32; o <<= 1) {
            int v = __shfl_up_sync(0xFFFFFFFFu, pre, o);
            if (w >= o) pre += v;
        }
        int total = __shfl_sync(0xFFFFFFFFu, pre, 31);
        pre -= cnt;
        float* ob = dout + (size_t)img * MAXDET * 4;
        float* os = dout + (size_t)NB_IMG * MAXDET * 4 + (size_t)img * MAXDET;
        float* ol = dout + (size_t)NB_IMG * MAXDET * 5 + (size_t)img * MAXDET;
        unsigned m = mykeep;
        int r = pre;
        while (m) {
            int b = __ffs(m) - 1; m &= m - 1;
            if (r < MAXDET) {
                int i = w * 32 + b;
                ob[r * 4 + 0] = g_box[img][i][0];
                ob[r * 4 + 1] = g_box[img][i][1];
                ob[r * 4 + 2] = g_box[img][i][2];
                ob[r * 4 + 3] = g_box[img][i][3];
                os[r] = g_score[img][i];
                ol[r] = (float)g_label[img][i];
            }
            r++;
        }
        for (int r2 = total + w; r2 < MAXDET; r2 += 32) {
            ob[r2 * 4 + 0] = 0.0f; ob[r2 * 4 + 1] = 0.0f;
            ob[r2 * 4 + 2] = 0.0f; ob[r2 * 4 + 3] = 0.0f;
            os[r2] = 0.0f;
            ol[r2] = -1.0f;
        }
    }
}

// ---------------------------------------------------------------- launch
extern "C" void kernel_launch(void* const* d_in, const int* in_sizes, int n_in,
                              void* d_out, int out_size) {
    (void)in_sizes; (void)n_in; (void)out_size;
    const float* preds = (const float*)d_in[0];
    float* out = (float*)d_out;

    cudaFuncSetAttribute(k_final, cudaFuncAttributeMaxDynamicSharedMemorySize, 132 * 1024);

    dim3 gScan((NA + 255) / 256, NB_IMG);
    k_zero<<<(NB_IMG * NBINS + 255) / 256, 256>>>();
    k_scan<<<gScan, 256>>>(preds);
    k_thr<<<NB_IMG, 256>>>();
    k_fbhist<<<gScan, 256>>>(preds);
    k_fbthr<<<NB_IMG, 256>>>();
    k_fbcompact<<<gScan, 256>>>(preds);
    k_prep<<<NB_IMG, 1024>>>(preds);
    k_mask<<<dim3(128, NB_IMG), 256>>>();
    k_final<<<NB_IMG, 1024, PRE * 32 * sizeof(unsigned)>>>(out);
}

// round 3
// speedup vs baseline: 1.2434x; 1.2434x over previous
#include <cuda_runtime.h>
#include <cstdint>

#define NB_IMG   16
#define NA       22743
#define NCH      85
#define NCLS     80
#define PRE      1000
#define PADN     1024
#define SORTN    4096
#define CAP      32768
#define NBINS    8192
#define MAXDET   300
#define CONF_TH  0.2f
#define NMS_TH   0.45f
#define NGROUP   ((NB_IMG * NA * NCH) / 340)   // 90972 exact

static __device__ __constant__ unsigned B09 = 0x3F666666u; // bits(0.9f)

__device__ unsigned            g_hist[NB_IMG][NBINS];
__device__ unsigned            g_hist2[NB_IMG][NBINS];
__device__ unsigned            g_candcnt[NB_IMG];
__device__ unsigned long long  g_cand[NB_IMG][CAP];
__device__ unsigned            g_thr[NB_IMG];
__device__ int                 g_flag[NB_IMG];
__device__ float               g_box[NB_IMG][PADN][4];
__device__ float               g_sbox[NB_IMG][PADN][4];
__device__ float               g_sarea[NB_IMG][PADN];
__device__ float               g_score[NB_IMG][PADN];
__device__ int                 g_label[NB_IMG][PADN];
__device__ unsigned            g_lblbits[NB_IMG][NCLS][32];
__device__ unsigned            g_mask[NB_IMG][PADN][32];

// ---------------------------------------------------------------- zero
__global__ void k_zero() {
    int i = blockIdx.x * blockDim.x + threadIdx.x;
    if (i < NB_IMG * NBINS) {
        (&g_hist[0][0])[i]  = 0u;
        (&g_hist2[0][0])[i] = 0u;
    }
    if (i < NB_IMG) g_candcnt[i] = 0u;
}

// ---------------------------------------------------------------- emit helper
__device__ __forceinline__ void emit_cand(float s, unsigned e) {
    unsigned a  = e / 85u;
    unsigned ch = e - a * 85u;
    if (ch >= 5u) {
        unsigned img  = a / (unsigned)NA;
        unsigned arow = a - img * (unsigned)NA;
        unsigned bits = __float_as_uint(s);
        unsigned bin  = (bits - (B09 + 1u)) >> 8;
        if (bin > NBINS - 1) bin = NBINS - 1;
        atomicAdd(&g_hist[img][bin], 1u);
        unsigned pos = atomicAdd(&g_candcnt[img], 1u);
        if (pos < CAP)
            g_cand[img][pos] = ((unsigned long long)bits << 32) |
                               (unsigned long long)(0xFFFFFFFFu - (arow * NCLS + (ch - 5u)));
    }
}

// ---------------------------------------------------------------- main scan
// One warp per 340 consecutive floats (= 4 rows, always 16B aligned).
__global__ void k_scan(const float* __restrict__ preds) {
    unsigned wid  = (blockIdx.x * blockDim.x + threadIdx.x) >> 5;
    int      lane = threadIdx.x & 31;
    if (wid >= NGROUP) return;
    const float4* b4 = (const float4*)preds + (size_t)wid * 85;
    const float*  bf = preds + (size_t)wid * 340;

    float c0 = __ldg(bf + 4);
    float c1 = __ldg(bf + 89);
    float c2 = __ldg(bf + 174);
    float c3 = __ldg(bf + 259);

    float4 v0 = b4[lane];
    float4 v1 = b4[lane + 32];
    float4 v2 = make_float4(0.f, 0.f, 0.f, 0.f);
    if (lane < 21) v2 = b4[lane + 64];

    float m = fmaxf(fmaxf(fmaxf(v0.x, v0.y), fmaxf(v0.z, v0.w)),
                    fmaxf(fmaxf(v1.x, v1.y), fmaxf(v1.z, v1.w)));
    m = fmaxf(m, fmaxf(fmaxf(v2.x, v2.y), fmaxf(v2.z, v2.w)));
    float cmax = fmaxf(fmaxf(c0, c1), fmaxf(c2, c3));

    if (m * cmax > 0.9f) {
        unsigned eb = wid * 340u;
        // exact per-element confs (row boundaries at local e = 85,170,255)
        float a0 = (lane >= 22) ? c1 : c0;
        float a1 = (lane >= 21) ? c1 : c0;
        float b0 = (lane >= 11) ? c2 : c1;
        float b2 = (lane >= 10) ? c2 : c1;
        float b3 = (lane == 31) ? c3 : b2;
        float s;
        s = v0.x * a0; if (s > 0.9f) emit_cand(s, eb + 4*lane + 0);
        s = v0.y * a1; if (s > 0.9f) emit_cand(s, eb + 4*lane + 1);
        s = v0.z * a1; if (s > 0.9f) emit_cand(s, eb + 4*lane + 2);
        s = v0.w * a1; if (s > 0.9f) emit_cand(s, eb + 4*lane + 3);
        s = v1.x * b0; if (s > 0.9f) emit_cand(s, eb + 128 + 4*lane + 0);
        s = v1.y * b0; if (s > 0.9f) emit_cand(s, eb + 128 + 4*lane + 1);
        s = v1.z * b2; if (s > 0.9f) emit_cand(s, eb + 128 + 4*lane + 2);
        s = v1.w * b3; if (s > 0.9f) emit_cand(s, eb + 128 + 4*lane + 3);
        if (lane < 21) {
            s = v2.x * c3; if (s > 0.9f) emit_cand(s, eb + 256 + 4*lane + 0);
            s = v2.y * c3; if (s > 0.9f) emit_cand(s, eb + 256 + 4*lane + 1);
            s = v2.z * c3; if (s > 0.9f) emit_cand(s, eb + 256 + 4*lane + 2);
            s = v2.w * c3; if (s > 0.9f) emit_cand(s, eb + 256 + 4*lane + 3);
        }
    }
}

// ---------------------------------------------------------------- threshold from fine hist
__global__ void k_thr() {
    __shared__ unsigned sh[NBINS];
    __shared__ unsigned csum[256];
    int img = blockIdx.x, tid = threadIdx.x;
    for (int i = tid; i < NBINS; i += 256) sh[i] = g_hist[img][i];
    __syncthreads();
    unsigned ssum = 0;
    for (int j = 0; j < 32; j++) ssum += sh[tid * 32 + j];
    csum[tid] = ssum;
    __syncthreads();
    if (tid == 0) {
        unsigned total = 0;
        for (int c = 0; c < 256; c++) total += csum[c];
        if (total >= PRE) {
            unsigned acc = 0, M = 0;
            int bstar = 0;
            for (int c = 255; c >= 0; c--) {
                if (acc + csum[c] >= PRE) {
                    for (int b = c * 32 + 31; b >= c * 32; b--) {
                        acc += sh[b];
                        if (acc >= PRE) { bstar = b; M = acc; break; }
                    }
                    break;
                }
                acc += csum[c];
            }
            if (M > SORTN) { bstar++; }   // pathological ties
            g_thr[img]  = B09 + 1u + ((unsigned)bstar << 8);
            g_flag[img] = 0;
        } else {
            g_candcnt[img] = 0;
            g_flag[img]    = 1;
        }
    }
}

// ---------------------------------------------------------------- fallback (rare)
__global__ void k_fbhist(const float* __restrict__ preds) {
    int img = blockIdx.y;
    if (g_flag[img] != 1) return;
    int a = blockIdx.x * blockDim.x + threadIdx.x;
    if (a >= NA) return;
    const float* p = preds + ((size_t)(img * NA + a)) * NCH;
    float conf = p[4];
    for (int c = 0; c < NCLS; c++) {
        float s = p[5 + c] * conf;
        if (s > CONF_TH) {
            unsigned bin = __float_as_uint(s) >> 13;
            if (bin > NBINS - 1) bin = NBINS - 1;
            atomicAdd(&g_hist2[img][bin], 1u);
        }
    }
}

__global__ void k_fbthr() {
    int img = blockIdx.x;
    if (g_flag[img] != 1) return;
    __shared__ unsigned sh[NBINS];
    __shared__ unsigned csum[256];
    int tid = threadIdx.x;
    for (int i = tid; i < NBINS; i += 256) sh[i] = g_hist2[img][i];
    __syncthreads();
    unsigned ssum = 0;
    for (int j = 0; j < 32; j++) ssum += sh[tid * 32 + j];
    csum[tid] = ssum;
    __syncthreads();
    if (tid == 0) {
        unsigned total = 0;
        for (int c = 0; c < 256; c++) total += csum[c];
        if (total >= PRE) {
            unsigned acc = 0, M = 0;
            int bstar = 0;
            for (int c = 255; c >= 0; c--) {
                if (acc + csum[c] >= PRE) {
                    for (int b = c * 32 + 31; b >= c * 32; b--) {
                        acc += sh[b];
                        if (acc >= PRE) { bstar = b; M = acc; break; }
                    }
                    break;
                }
                acc += csum[c];
            }
            if (M > SORTN) { bstar++; }
            g_thr[img] = (unsigned)bstar << 13;
        } else {
            g_thr[img] = 0;          // select everything > 0.2
        }
    }
}

__global__ void k_fbcompact(const float* __restrict__ preds) {
    int img = blockIdx.y;
    if (g_flag[img] == 0) return;
    int a = blockIdx.x * blockDim.x + threadIdx.x;
    if (a >= NA) return;
    unsigned thr = g_thr[img];
    const float* p = preds + ((size_t)(img * NA + a)) * NCH;
    float conf = p[4];
    unsigned flatbase = (unsigned)a * NCLS;
    for (int c = 0; c < NCLS; c++) {
        float s = p[5 + c] * conf;
        if (s > CONF_TH) {
            unsigned bits = __float_as_uint(s);
            if (bits >= thr) {
                unsigned pos = atomicAdd(&g_candcnt[img], 1u);
                if (pos < CAP)
                    g_cand[img][pos] = ((unsigned long long)bits << 32) |
                                       (unsigned long long)(0xFFFFFFFFu - (flatbase + (unsigned)c));
            }
        }
    }
}

// ---------------------------------------------------------------- sort + gather + shift + label bitsets
__global__ void k_prep(const float* __restrict__ preds) {
    __shared__ unsigned long long keys[SORTN];
    __shared__ unsigned scnt;
    __shared__ float wmax[32];
    __shared__ float s_maxv;
    __shared__ unsigned sbits[NCLS][32];
    int img = blockIdx.x, tid = threadIdx.x;
    unsigned thr = g_thr[img];
    unsigned n   = g_candcnt[img]; if (n > CAP) n = CAP;
    if (tid == 0) scnt = 0;
    for (int i = tid; i < SORTN; i += 1024) keys[i] = 0ULL;
    for (int i = tid; i < NCLS * 32; i += 1024) (&sbits[0][0])[i] = 0u;
    __syncthreads();
    for (unsigned i = tid; i < n; i += 1024) {
        unsigned long long k = g_cand[img][i];
        if ((unsigned)(k >> 32) >= thr) {
            unsigned pos = atomicAdd(&scnt, 1u);
            if (pos < SORTN) keys[pos] = k;
        }
    }
    __syncthreads();
    int n2 = (scnt <= 2048u) ? 2048 : SORTN;
    // bitonic sort, descending
    for (int k2 = 2; k2 <= n2; k2 <<= 1)
        for (int j = k2 >> 1; j > 0; j >>= 1) {
            for (int idx = tid; idx < n2; idx += 1024) {
                int ixj = idx ^ j;
                if (ixj > idx) {
                    unsigned long long x = keys[idx], y = keys[ixj];
                    bool asc  = (idx & k2) != 0;
                    bool swap = asc ? (x > y) : (x < y);
                    if (swap) { keys[idx] = y; keys[ixj] = x; }
                }
            }
            __syncthreads();
        }
    // decode row tid
    float bx0 = 0.f, bx1 = 0.f, bx2 = 0.f, bx3 = 0.f, s = 0.f;
    int lab = 0;
    float localmax = 0.0f;
    if (tid < PRE) {
        unsigned long long k = keys[tid];
        if (k != 0ULL) {
            unsigned bits = (unsigned)(k >> 32);
            s = __uint_as_float(bits);
            unsigned flat = 0xFFFFFFFFu - (unsigned)(k & 0xFFFFFFFFull);
            int anc = (int)(flat / NCLS);
            lab     = (int)(flat % NCLS);
            const float* bp = preds + ((size_t)(img * NA + anc)) * NCH;
            bx0 = bp[0]; bx1 = bp[1]; bx2 = bp[2]; bx3 = bp[3];
        }
        localmax = fmaxf(fmaxf(bx0, bx1), fmaxf(bx2, bx3));
        g_score[img][tid]  = s;
        g_label[img][tid]  = lab;
        g_box[img][tid][0] = bx0; g_box[img][tid][1] = bx1;
        g_box[img][tid][2] = bx2; g_box[img][tid][3] = bx3;
        atomicOr(&sbits[lab][tid >> 5], 1u << (tid & 31));
    }
    for (int o = 16; o; o >>= 1) localmax = fmaxf(localmax, __shfl_xor_sync(0xFFFFFFFFu, localmax, o));
    if ((tid & 31) == 0) wmax[tid >> 5] = localmax;
    __syncthreads();
    if (tid < 32) {
        float v = wmax[tid];
        for (int o = 16; o; o >>= 1) v = fmaxf(v, __shfl_xor_sync(0xFFFFFFFFu, v, o));
        if (tid == 0) s_maxv = v;
    }
    __syncthreads();
    float maxv = s_maxv;
    if (tid < PRE) {
        float shift = (float)lab * (maxv + 1.0f);
        float x1 = bx0 + shift, y1 = bx1 + shift, x2 = bx2 + shift, y2 = bx3 + shift;
        g_sbox[img][tid][0] = x1; g_sbox[img][tid][1] = y1;
        g_sbox[img][tid][2] = x2; g_sbox[img][tid][3] = y2;
        g_sarea[img][tid] = fmaxf(x2 - x1, 0.0f) * fmaxf(y2 - y1, 0.0f);
    }
    for (int i = tid; i < NCLS * 32; i += 1024)
        (&g_lblbits[img][0][0])[i] = (&sbits[0][0])[i];
}

// ---------------------------------------------------------------- suppression mask (same-label pairs only)
__global__ void k_mask() {
    int img = blockIdx.y;
    int tid = threadIdx.x;
    int i   = blockIdx.x * 8 + (tid >> 5);
    int w   = tid & 31;
    unsigned out = 0u;
    if (i < PRE) {
        int l = g_label[img][i];
        unsigned cand = g_lblbits[img][l][w];
        int wi = i >> 5;
        if (w < wi) cand = 0u;
        else if (w == wi) cand &= ~((2u << (i & 31)) - 1u);
        if (cand) {
            float x1 = g_sbox[img][i][0], y1 = g_sbox[img][i][1];
            float x2 = g_sbox[img][i][2], y2 = g_sbox[img][i][3];
            float ai = g_sarea[img][i];
            unsigned mm = cand;
            while (mm) {
                int bb = __ffs(mm) - 1; mm &= mm - 1;
                int j = w * 32 + bb;
                float xj1 = g_sbox[img][j][0], yj1 = g_sbox[img][j][1];
                float xj2 = g_sbox[img][j][2], yj2 = g_sbox[img][j][3];
                float ix1 = fmaxf(x1, xj1), iy1 = fmaxf(y1, yj1);
                float ix2 = fminf(x2, xj2), iy2 = fminf(y2, yj2);
                float inter = fmaxf(ix2 - ix1, 0.0f) * fmaxf(iy2 - iy1, 0.0f);
                float den = ai + g_sarea[img][j];
                den = den - inter;
                den = den + 1e-7f;
                float iou = __fdiv_rn(inter, den);
                if (iou > NMS_TH) out |= (1u << bb);
            }
        }
    }
    if (i < PRE) g_mask[img][i][w] = out;
}

// ---------------------------------------------------------------- serial NMS reduce + output
__global__ void k_final(float* __restrict__ dout) {
    extern __shared__ unsigned smask[];   // PRE*32 words
    int img = blockIdx.x, tid = threadIdx.x;
    const unsigned* gm = &g_mask[img][0][0];
    for (int i = tid; i < PRE * 32; i += 1024) smask[i] = gm[i];
    __syncthreads();
    if (tid < 32) {
        int w = tid;
        unsigned valid = 0u;
        for (int b = 0; b < 32; b++) {
            int i = w * 32 + b;
            if (i < PRE && g_score[img][i] > CONF_TH) valid |= (1u << b);
        }
        unsigned removed = 0u, mykeep = 0u;
        for (int W = 0; W < 32; W++) {
            unsigned kw = 0u;
            if (w == W) {
                unsigned rW = removed;
                for (int b = 0; b < 32; b++) {
                    int i = W * 32 + b;
                    if (i >= PRE) break;
                    if (((valid >> b) & 1u) && !((rW >> b) & 1u)) {
                        kw |= (1u << b);
                        rW |= smask[i * 32 + W];
                    }
                }
                removed = rW;
            }
            kw = __shfl_sync(0xFFFFFFFFu, kw, W);
            unsigned m = kw;
            while (m) {
                int b = __ffs(m) - 1; m &= m - 1;
                removed |= smask[(W * 32 + b) * 32 + w];
            }
            if (w == W) mykeep = kw;
            __syncwarp();
        }
        int cnt = __popc(mykeep);
        int pre = cnt;
        for (int o = 1; o < 32; o <<= 1) {
            int v = __shfl_up_sync(0xFFFFFFFFu, pre, o);
            if (w >= o) pre += v;
        }
        int total = __shfl_sync(0xFFFFFFFFu, pre, 31);
        pre -= cnt;
        float* ob = dout + (size_t)img * MAXDET * 4;
        float* os = dout + (size_t)NB_IMG * MAXDET * 4 + (size_t)img * MAXDET;
        float* ol = dout + (size_t)NB_IMG * MAXDET * 5 + (size_t)img * MAXDET;
        unsigned m = mykeep;
        int r = pre;
        while (m) {
            int b = __ffs(m) - 1; m &= m - 1;
            if (r < MAXDET) {
                int i = w * 32 + b;
                ob[r * 4 + 0] = g_box[img][i][0];
                ob[r * 4 + 1] = g_box[img][i][1];
                ob[r * 4 + 2] = g_box[img][i][2];
                ob[r * 4 + 3] = g_box[img][i][3];
                os[r] = g_score[img][i];
                ol[r] = (float)g_label[img][i];
            }
            r++;
        }
        for (int r2 = total + w; r2 < MAXDET; r2 += 32) {
            ob[r2 * 4 + 0] = 0.0f; ob[r2 * 4 + 1] = 0.0f;
            ob[r2 * 4 + 2] = 0.0f; ob[r2 * 4 + 3] = 0.0f;
            os[r2] = 0.0f;
            ol[r2] = -1.0f;
        }
    }
}

// ---------------------------------------------------------------- launch
extern "C" void kernel_launch(void* const* d_in, const int* in_sizes, int n_in,
                              void* d_out, int out_size) {
    (void)in_sizes; (void)n_in; (void)out_size;
    const float* preds = (const float*)d_in[0];
    float* out = (float*)d_out;

    cudaFuncSetAttribute(k_final, cudaFuncAttributeMaxDynamicSharedMemorySize, 132 * 1024);

    dim3 gFb((NA + 255) / 256, NB_IMG);
    k_zero<<<(NB_IMG * NBINS + 255) / 256, 256>>>();
    k_scan<<<(NGROUP * 32 + 255) / 256, 256>>>(preds);
    k_thr<<<NB_IMG, 256>>>();
    k_fbhist<<<gFb, 256>>>(preds);
    k_fbthr<<<NB_IMG, 256>>>();
    k_fbcompact<<<gFb, 256>>>(preds);
    k_prep<<<NB_IMG, 1024>>>(preds);
    k_mask<<<dim3(125, NB_IMG), 256>>>();
    k_final<<<NB_IMG, 1024, PRE * 32 * sizeof(unsigned)>>>(out);
}

// round 4
// speedup vs baseline: 2.6806x; 2.1559x over previous
#include <cuda_runtime.h>
#include <cstdint>

#define NB_IMG   16
#define NA       22743
#define NCH      85
#define NCLS     80
#define PRE      1000
#define PADN     1024
#define SORTN    4096
#define CAP      32768
#define NBINS    8192
#define MAXDET   300
#define CONF_TH  0.2f
#define NMS_TH   0.45f

static __device__ __constant__ unsigned B09 = 0x3F666666u; // bits(0.9f)

__device__ unsigned            g_hist[NB_IMG][NBINS];
__device__ unsigned            g_candcnt[NB_IMG];
__device__ unsigned long long  g_cand[NB_IMG][CAP];
__device__ unsigned            g_thr[NB_IMG];
__device__ float               g_box[NB_IMG][PADN][4];
__device__ float               g_sbox[NB_IMG][PADN][4];
__device__ float               g_sarea[NB_IMG][PADN];
__device__ float               g_score[NB_IMG][PADN];
__device__ int                 g_label[NB_IMG][PADN];
__device__ unsigned            g_lblbits[NB_IMG][NCLS][32];
__device__ unsigned            g_mask[NB_IMG][PADN][32];

// ---------------------------------------------------------------- zero
__global__ void k_zero() {
    int i = blockIdx.x * blockDim.x + threadIdx.x;
    if (i < NB_IMG * NBINS) (&g_hist[0][0])[i] = 0u;
    if (i < NB_IMG) g_candcnt[i] = 0u;
}

// ---------------------------------------------------------------- scan
// Phase A: each thread reads one conf; block-compacts hot anchors (conf>0.9)
// to smem. Phase B: one warp per hot anchor scans its 80 classprobs.
// Valid because classprobs < 1 => fl(p*conf) <= conf, so score>0.9 => conf>0.9.
__global__ void k_scan(const float* __restrict__ preds) {
    __shared__ int      s_hot[256];
    __shared__ float    s_conf[256];
    __shared__ unsigned s_n;
    int img = blockIdx.y;
    int a   = blockIdx.x * 256 + threadIdx.x;
    if (threadIdx.x == 0) s_n = 0;
    __syncthreads();
    float conf = 0.0f;
    if (a < NA) conf = __ldg(preds + ((size_t)img * NA + a) * NCH + 4);
    if (conf > 0.9f) {
        unsigned p = atomicAdd(&s_n, 1u);
        s_hot[p]  = a;
        s_conf[p] = conf;
    }
    __syncthreads();
    int nhot = (int)s_n;
    int wid  = threadIdx.x >> 5, lane = threadIdx.x & 31;
    for (int h = wid; h < nhot; h += 8) {
        int   aa = s_hot[h];
        float cf = s_conf[h];
        const float* pp = preds + ((size_t)img * NA + aa) * NCH + 5;
        float p0 = __ldg(pp + lane);
        float p1 = __ldg(pp + lane + 32);
        float p2 = (lane < 16) ? __ldg(pp + lane + 64) : 0.0f;
        float s0 = p0 * cf, s1 = p1 * cf, s2 = p2 * cf;
        bool e0 = s0 > 0.9f, e1 = s1 > 0.9f, e2 = s2 > 0.9f;
        unsigned b0 = __ballot_sync(0xFFFFFFFFu, e0);
        unsigned b1 = __ballot_sync(0xFFFFFFFFu, e1);
        unsigned b2 = __ballot_sync(0xFFFFFFFFu, e2);
        unsigned tot = __popc(b0) + __popc(b1) + __popc(b2);
        if (tot) {
            unsigned base = 0;
            if (lane == 0) base = atomicAdd(&g_candcnt[img], tot);
            base = __shfl_sync(0xFFFFFFFFu, base, 0);
            unsigned lt = (1u << lane) - 1u;
            unsigned fb = (unsigned)aa * NCLS;
            if (e0) {
                unsigned bits = __float_as_uint(s0);
                unsigned bin = (bits - (B09 + 1u)) >> 8; if (bin > NBINS - 1) bin = NBINS - 1;
                atomicAdd(&g_hist[img][bin], 1u);
                unsigned slot = base + __popc(b0 & lt);
                if (slot < CAP)
                    g_cand[img][slot] = ((unsigned long long)bits << 32) |
                        (unsigned long long)(0xFFFFFFFFu - (fb + lane));
            }
            if (e1) {
                unsigned bits = __float_as_uint(s1);
                unsigned bin = (bits - (B09 + 1u)) >> 8; if (bin > NBINS - 1) bin = NBINS - 1;
                atomicAdd(&g_hist[img][bin], 1u);
                unsigned slot = base + __popc(b0) + __popc(b1 & lt);
                if (slot < CAP)
                    g_cand[img][slot] = ((unsigned long long)bits << 32) |
                        (unsigned long long)(0xFFFFFFFFu - (fb + lane + 32u));
            }
            if (e2) {
                unsigned bits = __float_as_uint(s2);
                unsigned bin = (bits - (B09 + 1u)) >> 8; if (bin > NBINS - 1) bin = NBINS - 1;
                atomicAdd(&g_hist[img][bin], 1u);
                unsigned slot = base + __popc(b0) + __popc(b1) + __popc(b2 & lt);
                if (slot < CAP)
                    g_cand[img][slot] = ((unsigned long long)bits << 32) |
                        (unsigned long long)(0xFFFFFFFFu - (fb + lane + 64u));
            }
        }
    }
}

// ---------------------------------------------------------------- threshold + inline fallback
__global__ void k_thrfb(const float* __restrict__ preds) {
    __shared__ unsigned sh[NBINS];
    __shared__ unsigned csum[256];
    __shared__ int      s_fb;
    __shared__ unsigned s_thr;
    int img = blockIdx.x, tid = threadIdx.x;
    for (int i = tid; i < NBINS; i += 1024) sh[i] = g_hist[img][i];
    __syncthreads();
    if (tid < 256) {
        unsigned ssum = 0;
        for (int j = 0; j < 32; j++) ssum += sh[tid * 32 + j];
        csum[tid] = ssum;
    }
    __syncthreads();
    if (tid == 0) {
        unsigned total = 0;
        for (int c = 0; c < 256; c++) total += csum[c];
        if (total >= PRE) {
            unsigned acc = 0, M = 0;
            int bstar = 0;
            for (int c = 255; c >= 0; c--) {
                if (acc + csum[c] >= PRE) {
                    for (int b = c * 32 + 31; b >= c * 32; b--) {
                        acc += sh[b];
                        if (acc >= PRE) { bstar = b; M = acc; break; }
                    }
                    break;
                }
                acc += csum[c];
            }
            if (M > SORTN) bstar++;               // pathological ties
            g_thr[img] = B09 + 1u + ((unsigned)bstar << 8);
            s_fb = 0;
        } else {
            g_candcnt[img] = 0u;
            s_fb = 1;
        }
    }
    __syncthreads();
    if (s_fb == 0) return;

    // ---- fallback (rare): full-range histogram over whole image, in-block ----
    for (int i = tid; i < NBINS; i += 1024) sh[i] = 0u;
    __syncthreads();
    const float* base = preds + (size_t)img * NA * NCH;
    for (int a = tid; a < NA; a += 1024) {
        const float* p = base + (size_t)a * NCH;
        float conf = p[4];
        for (int c = 0; c < NCLS; c++) {
            float s = p[5 + c] * conf;
            if (s > CONF_TH) {
                unsigned bin = __float_as_uint(s) >> 13;
                if (bin > NBINS - 1) bin = NBINS - 1;
                atomicAdd(&sh[bin], 1u);
            }
        }
    }
    __syncthreads();
    if (tid < 256) {
        unsigned ssum = 0;
        for (int j = 0; j < 32; j++) ssum += sh[tid * 32 + j];
        csum[tid] = ssum;
    }
    __syncthreads();
    if (tid == 0) {
        unsigned total = 0;
        for (int c = 0; c < 256; c++) total += csum[c];
        unsigned thr = 0;
        if (total >= PRE) {
            unsigned acc = 0, M = 0;
            int bstar = 0;
            for (int c = 255; c >= 0; c--) {
                if (acc + csum[c] >= PRE) {
                    for (int b = c * 32 + 31; b >= c * 32; b--) {
                        acc += sh[b];
                        if (acc >= PRE) { bstar = b; M = acc; break; }
                    }
                    break;
                }
                acc += csum[c];
            }
            if (M > SORTN) bstar++;
            thr = (unsigned)bstar << 13;
        }
        g_thr[img] = thr;
        s_thr = thr;
    }
    __syncthreads();
    unsigned thr = s_thr;
    for (int a = tid; a < NA; a += 1024) {
        const float* p = base + (size_t)a * NCH;
        float conf = p[4];
        unsigned fb = (unsigned)a * NCLS;
        for (int c = 0; c < NCLS; c++) {
            float s = p[5 + c] * conf;
            if (s > CONF_TH) {
                unsigned bits = __float_as_uint(s);
                if (bits >= thr) {
                    unsigned pos = atomicAdd(&g_candcnt[img], 1u);
                    if (pos < CAP)
                        g_cand[img][pos] = ((unsigned long long)bits << 32) |
                            (unsigned long long)(0xFFFFFFFFu - (fb + (unsigned)c));
                }
            }
        }
    }
}

// ---------------------------------------------------------------- sort + gather + shift + label bitsets
__global__ void k_prep(const float* __restrict__ preds) {
    __shared__ unsigned long long keys[SORTN];
    __shared__ unsigned scnt;
    __shared__ float wmax[32];
    __shared__ float s_maxv;
    __shared__ unsigned sbits[NCLS][32];
    int img = blockIdx.x, tid = threadIdx.x;
    unsigned thr = g_thr[img];
    unsigned n   = g_candcnt[img]; if (n > CAP) n = CAP;
    if (tid == 0) scnt = 0;
    for (int i = tid; i < SORTN; i += 1024) keys[i] = 0ULL;
    for (int i = tid; i < NCLS * 32; i += 1024) (&sbits[0][0])[i] = 0u;
    __syncthreads();
    for (unsigned i = tid; i < n; i += 1024) {
        unsigned long long k = g_cand[img][i];
        if ((unsigned)(k >> 32) >= thr) {
            unsigned pos = atomicAdd(&scnt, 1u);
            if (pos < SORTN) keys[pos] = k;
        }
    }
    __syncthreads();
    int n2 = (scnt <= 2048u) ? 2048 : SORTN;
    for (int k2 = 2; k2 <= n2; k2 <<= 1)
        for (int j = k2 >> 1; j > 0; j >>= 1) {
            for (int idx = tid; idx < n2; idx += 1024) {
                int ixj = idx ^ j;
                if (ixj > idx) {
                    unsigned long long x = keys[idx], y = keys[ixj];
                    bool asc  = (idx & k2) != 0;
                    bool swap = asc ? (x > y) : (x < y);
                    if (swap) { keys[idx] = y; keys[ixj] = x; }
                }
            }
            __syncthreads();
        }
    float bx0 = 0.f, bx1 = 0.f, bx2 = 0.f, bx3 = 0.f, s = 0.f;
    int lab = 0;
    float localmax = 0.0f;
    if (tid < PRE) {
        unsigned long long k = keys[tid];
        if (k != 0ULL) {
            unsigned bits = (unsigned)(k >> 32);
            s = __uint_as_float(bits);
            unsigned flat = 0xFFFFFFFFu - (unsigned)(k & 0xFFFFFFFFull);
            int anc = (int)(flat / NCLS);
            lab     = (int)(flat % NCLS);
            const float* bp = preds + ((size_t)(img * NA + anc)) * NCH;
            bx0 = bp[0]; bx1 = bp[1]; bx2 = bp[2]; bx3 = bp[3];
        }
        localmax = fmaxf(fmaxf(bx0, bx1), fmaxf(bx2, bx3));
        g_score[img][tid]  = s;
        g_label[img][tid]  = lab;
        g_box[img][tid][0] = bx0; g_box[img][tid][1] = bx1;
        g_box[img][tid][2] = bx2; g_box[img][tid][3] = bx3;
        atomicOr(&sbits[lab][tid >> 5], 1u << (tid & 31));
    }
    for (int o = 16; o; o >>= 1) localmax = fmaxf(localmax, __shfl_xor_sync(0xFFFFFFFFu, localmax, o));
    if ((tid & 31) == 0) wmax[tid >> 5] = localmax;
    __syncthreads();
    if (tid < 32) {
        float v = wmax[tid];
        for (int o = 16; o; o >>= 1) v = fmaxf(v, __shfl_xor_sync(0xFFFFFFFFu, v, o));
        if (tid == 0) s_maxv = v;
    }
    __syncthreads();
    float maxv = s_maxv;
    if (tid < PRE) {
        float shift = (float)lab * (maxv + 1.0f);
        float x1 = bx0 + shift, y1 = bx1 + shift, x2 = bx2 + shift, y2 = bx3 + shift;
        g_sbox[img][tid][0] = x1; g_sbox[img][tid][1] = y1;
        g_sbox[img][tid][2] = x2; g_sbox[img][tid][3] = y2;
        g_sarea[img][tid] = fmaxf(x2 - x1, 0.0f) * fmaxf(y2 - y1, 0.0f);
    }
    for (int i = tid; i < NCLS * 32; i += 1024)
        (&g_lblbits[img][0][0])[i] = (&sbits[0][0])[i];
}

// ---------------------------------------------------------------- suppression mask (smem-staged)
// block 1024 = 32 rows x 32 words; grid (32, 16)
__global__ void k_mask() {
    __shared__ float4   sb[PADN];
    __shared__ float    sa[PADN];
    __shared__ int      sl[PADN];
    __shared__ unsigned slb[NCLS][32];
    int img = blockIdx.y, tid = threadIdx.x;
    for (int i = tid; i < PADN; i += 1024) {
        sb[i] = ((const float4*)g_sbox[img])[i];
        sa[i] = g_sarea[img][i];
        sl[i] = g_label[img][i];
    }
    for (int i = tid; i < NCLS * 32; i += 1024)
        (&slb[0][0])[i] = (&g_lblbits[img][0][0])[i];
    __syncthreads();
    int i = blockIdx.x * 32 + (tid >> 5);
    int w = tid & 31;
    unsigned out = 0u;
    if (i < PRE) {
        int l = sl[i];
        unsigned cand = slb[l][w];
        int wi = i >> 5;
        if (w < wi) cand = 0u;
        else if (w == wi) cand &= ~((2u << (i & 31)) - 1u);
        if (cand) {
            float4 bi = sb[i];
            float  ai = sa[i];
            unsigned mm = cand;
            while (mm) {
                int bb = __ffs(mm) - 1; mm &= mm - 1;
                int j = w * 32 + bb;
                float4 bj = sb[j];
                float ix1 = fmaxf(bi.x, bj.x), iy1 = fmaxf(bi.y, bj.y);
                float ix2 = fminf(bi.z, bj.z), iy2 = fminf(bi.w, bj.w);
                float inter = fmaxf(ix2 - ix1, 0.0f) * fmaxf(iy2 - iy1, 0.0f);
                float den = ai + sa[j];
                den = den - inter;
                den = den + 1e-7f;
                float iou = __fdiv_rn(inter, den);
                if (iou > NMS_TH) out |= (1u << bb);
            }
        }
        g_mask[img][i][w] = out;
    }
}

// ---------------------------------------------------------------- serial NMS reduce + output
__global__ void k_final(float* __restrict__ dout) {
    extern __shared__ unsigned smask[];   // PRE*32 words
    int img = blockIdx.x, tid = threadIdx.x;
    const uint4* gm4 = (const uint4*)&g_mask[img][0][0];
    uint4* sm4 = (uint4*)smask;
    for (int i = tid; i < PRE * 8; i += 1024) sm4[i] = gm4[i];
    __syncthreads();
    if (tid < 32) {
        int w = tid;
        unsigned valid = 0u;
        for (int b = 0; b < 32; b++) {
            int i = w * 32 + b;
            if (i < PRE && g_score[img][i] > CONF_TH) valid |= (1u << b);
        }
        unsigned removed = 0u, mykeep = 0u;
        for (int W = 0; W < 32; W++) {
            unsigned kw = 0u;
            if (w == W) {
                unsigned rW = removed;
                for (int b = 0; b < 32; b++) {
                    int i = W * 32 + b;
                    if (i >= PRE) break;
                    if (((valid >> b) & 1u) && !((rW >> b) & 1u)) {
                        kw |= (1u << b);
                        rW |= smask[i * 32 + W];
                    }
                }
                removed = rW;
            }
            kw = __shfl_sync(0xFFFFFFFFu, kw, W);
            unsigned m = kw;
            while (m) {
                int b = __ffs(m) - 1; m &= m - 1;
                removed |= smask[(W * 32 + b) * 32 + w];
            }
            if (w == W) mykeep = kw;
            __syncwarp();
        }
        int cnt = __popc(mykeep);
        int pre = cnt;
        for (int o = 1; o < 32; o <<= 1) {
            int v = __shfl_up_sync(0xFFFFFFFFu, pre, o);
            if (w >= o) pre += v;
        }
        int total = __shfl_sync(0xFFFFFFFFu, pre, 31);
        pre -= cnt;
        float* ob = dout + (size_t)img * MAXDET * 4;
        float* os = dout + (size_t)NB_IMG * MAXDET * 4 + (size_t)img * MAXDET;
        float* ol = dout + (size_t)NB_IMG * MAXDET * 5 + (size_t)img * MAXDET;
        unsigned m = mykeep;
        int r = pre;
        while (m) {
            int b = __ffs(m) - 1; m &= m - 1;
            if (r < MAXDET) {
                int i = w * 32 + b;
                ob[r * 4 + 0] = g_box[img][i][0];
                ob[r * 4 + 1] = g_box[img][i][1];
                ob[r * 4 + 2] = g_box[img][i][2];
                ob[r * 4 + 3] = g_box[img][i][3];
                os[r] = g_score[img][i];
                ol[r] = (float)g_label[img][i];
            }
            r++;
        }
        for (int r2 = total + w; r2 < MAXDET; r2 += 32) {
            ob[r2 * 4 + 0] = 0.0f; ob[r2 * 4 + 1] = 0.0f;
            ob[r2 * 4 + 2] = 0.0f; ob[r2 * 4 + 3] = 0.0f;
            os[r2] = 0.0f;
            ol[r2] = -1.0f;
        }
    }
}

// ---------------------------------------------------------------- launch
extern "C" void kernel_launch(void* const* d_in, const int* in_sizes, int n_in,
                              void* d_out, int out_size) {
    (void)in_sizes; (void)n_in; (void)out_size;
    const float* preds = (const float*)d_in[0];
    float* out = (float*)d_out;

    cudaFuncSetAttribute(k_final, cudaFuncAttributeMaxDynamicSharedMemorySize, 132 * 1024);

    k_zero<<<(NB_IMG * NBINS + 255) / 256, 256>>>();
    k_scan<<<dim3((NA + 255) / 256, NB_IMG), 256>>>(preds);
    k_thrfb<<<NB_IMG, 1024>>>(preds);
    k_prep<<<NB_IMG, 1024>>>(preds);
    k_mask<<<dim3(32, NB_IMG), 1024>>>();
    k_final<<<NB_IMG, 1024, PRE * 32 * sizeof(unsigned)>>>(out);
}